// round 1
// baseline (speedup 1.0000x reference)
#include <cuda_runtime.h>
#include <cstdint>

// Problem constants
#define BB 256   // batch
#define MM 96    // memory slots
#define WW 128   // write tokens
#define DD 512   // embed dim

// ---------------- scratch (static device globals: allocation-free) ----------
__device__ float g_q[BB * WW * DD];   // 67 MB
__device__ float g_e[BB * WW * DD];   // 67 MB (erase, post-sigmoid)
__device__ float g_a[BB * WW * DD];   // 67 MB (add, post-tanh)
__device__ float g_k[BB * MM * DD];   // 50 MB
__device__ float g_s[BB * WW * MM];   // 12.6 MB (scores -> attn in place)

// ---------------------------------------------------------------------------
// Generic C[r, j] = act( sum_d X[r,d] * W[j,d] + bias[j] )
// Tiles: BM=64 rows, BN=64 cols, BK=16. 256 threads, 4x4 per thread.
// act: 0=none, 1=sigmoid, 2=tanh
// ---------------------------------------------------------------------------
__global__ __launch_bounds__(256) void gemm_xwT_kernel(
    const float* __restrict__ X, const float* __restrict__ W,
    const float* __restrict__ bias, float* __restrict__ C, int act)
{
    __shared__ float As[16][64];
    __shared__ float Bs[16][64];

    const int bm = blockIdx.x;      // row tile
    const int bn = blockIdx.y;      // col tile (512/64 = 8)
    const int tid = threadIdx.x;
    const int tx = tid & 15;        // col dir
    const int ty = tid >> 4;        // row dir

    float acc[4][4];
#pragma unroll
    for (int i = 0; i < 4; i++)
#pragma unroll
        for (int j = 0; j < 4; j++) acc[i][j] = 0.f;

    const int lrow = tid >> 2;          // 0..63
    const int lcol = (tid & 3) * 4;     // 0,4,8,12
    const float* Xp = X + ((size_t)(bm * 64 + lrow)) * DD + lcol;
    const float* Wp = W + ((size_t)(bn * 64 + lrow)) * DD + lcol;

    for (int k0 = 0; k0 < DD; k0 += 16) {
        float4 xa = *(const float4*)(Xp + k0);
        float4 wb = *(const float4*)(Wp + k0);
        As[lcol + 0][lrow] = xa.x; As[lcol + 1][lrow] = xa.y;
        As[lcol + 2][lrow] = xa.z; As[lcol + 3][lrow] = xa.w;
        Bs[lcol + 0][lrow] = wb.x; Bs[lcol + 1][lrow] = wb.y;
        Bs[lcol + 2][lrow] = wb.z; Bs[lcol + 3][lrow] = wb.w;
        __syncthreads();
#pragma unroll
        for (int kk = 0; kk < 16; kk++) {
            float4 a = *(const float4*)&As[kk][ty * 4];
            float4 b = *(const float4*)&Bs[kk][tx * 4];
            acc[0][0] = fmaf(a.x, b.x, acc[0][0]); acc[0][1] = fmaf(a.x, b.y, acc[0][1]);
            acc[0][2] = fmaf(a.x, b.z, acc[0][2]); acc[0][3] = fmaf(a.x, b.w, acc[0][3]);
            acc[1][0] = fmaf(a.y, b.x, acc[1][0]); acc[1][1] = fmaf(a.y, b.y, acc[1][1]);
            acc[1][2] = fmaf(a.y, b.z, acc[1][2]); acc[1][3] = fmaf(a.y, b.w, acc[1][3]);
            acc[2][0] = fmaf(a.z, b.x, acc[2][0]); acc[2][1] = fmaf(a.z, b.y, acc[2][1]);
            acc[2][2] = fmaf(a.z, b.z, acc[2][2]); acc[2][3] = fmaf(a.z, b.w, acc[2][3]);
            acc[3][0] = fmaf(a.w, b.x, acc[3][0]); acc[3][1] = fmaf(a.w, b.y, acc[3][1]);
            acc[3][2] = fmaf(a.w, b.z, acc[3][2]); acc[3][3] = fmaf(a.w, b.w, acc[3][3]);
        }
        __syncthreads();
    }

    const int col = bn * 64 + tx * 4;
    float4 bb = *(const float4*)(bias + col);
#pragma unroll
    for (int i = 0; i < 4; i++) {
        float v0 = acc[i][0] + bb.x;
        float v1 = acc[i][1] + bb.y;
        float v2 = acc[i][2] + bb.z;
        float v3 = acc[i][3] + bb.w;
        if (act == 1) {
            v0 = 1.f / (1.f + __expf(-v0)); v1 = 1.f / (1.f + __expf(-v1));
            v2 = 1.f / (1.f + __expf(-v2)); v3 = 1.f / (1.f + __expf(-v3));
        } else if (act == 2) {
            v0 = tanhf(v0); v1 = tanhf(v1); v2 = tanhf(v2); v3 = tanhf(v3);
        }
        float4 v = make_float4(v0, v1, v2, v3);
        *(float4*)(C + ((size_t)(bm * 64 + ty * 4 + i)) * DD + col) = v;
    }
}

// ---------------------------------------------------------------------------
// scores[b, w, m] = scale * sum_d q[b,w,d] * k[b,m,d]
// Per block: one b, 64 w rows, all 96 m cols. 256 threads, 4x6 per thread.
// ---------------------------------------------------------------------------
__global__ __launch_bounds__(256) void scores_kernel(
    const float* __restrict__ Q, const float* __restrict__ K, float* __restrict__ S)
{
    __shared__ float qs[16][64];
    __shared__ float ks[16][96];

    const int b = blockIdx.y;
    const int w0 = blockIdx.x * 64;
    const int tid = threadIdx.x;
    const int tx = tid & 15;    // m dir: 6 each
    const int ty = tid >> 4;    // w dir: 4 each

    float acc[4][6];
#pragma unroll
    for (int i = 0; i < 4; i++)
#pragma unroll
        for (int j = 0; j < 6; j++) acc[i][j] = 0.f;

    const int qrow = tid >> 2;
    const int qcol = (tid & 3) * 4;
    const float* Qp = Q + ((size_t)(b * WW + w0 + qrow)) * DD + qcol;
    const float* Kb = K + (size_t)b * MM * DD;

    for (int k0 = 0; k0 < DD; k0 += 16) {
        float4 qa = *(const float4*)(Qp + k0);
        qs[qcol + 0][qrow] = qa.x; qs[qcol + 1][qrow] = qa.y;
        qs[qcol + 2][qrow] = qa.z; qs[qcol + 3][qrow] = qa.w;
        {
            int s = tid;                          // slots 0..255
            int kr = s >> 2, kc = (s & 3) * 4;
            float4 kv = *(const float4*)(Kb + (size_t)kr * DD + k0 + kc);
            ks[kc + 0][kr] = kv.x; ks[kc + 1][kr] = kv.y;
            ks[kc + 2][kr] = kv.z; ks[kc + 3][kr] = kv.w;
            if (tid < 128) {                      // slots 256..383
                s = tid + 256; kr = s >> 2; kc = (s & 3) * 4;
                kv = *(const float4*)(Kb + (size_t)kr * DD + k0 + kc);
                ks[kc + 0][kr] = kv.x; ks[kc + 1][kr] = kv.y;
                ks[kc + 2][kr] = kv.z; ks[kc + 3][kr] = kv.w;
            }
        }
        __syncthreads();
#pragma unroll
        for (int kk = 0; kk < 16; kk++) {
            float4 a = *(const float4*)&qs[kk][ty * 4];
            float2 p0 = *(const float2*)&ks[kk][tx * 6 + 0];
            float2 p1 = *(const float2*)&ks[kk][tx * 6 + 2];
            float2 p2 = *(const float2*)&ks[kk][tx * 6 + 4];
            float bj[6] = {p0.x, p0.y, p1.x, p1.y, p2.x, p2.y};
            float ai[4] = {a.x, a.y, a.z, a.w};
#pragma unroll
            for (int i = 0; i < 4; i++)
#pragma unroll
                for (int j = 0; j < 6; j++)
                    acc[i][j] = fmaf(ai[i], bj[j], acc[i][j]);
        }
        __syncthreads();
    }

    const float scale = 0.04419417382415922f;  // 1/sqrt(512)
#pragma unroll
    for (int i = 0; i < 4; i++) {
        float* row = S + ((size_t)(b * WW + w0 + ty * 4 + i)) * MM + tx * 6;
        float2 v0 = make_float2(acc[i][0] * scale, acc[i][1] * scale);
        float2 v1 = make_float2(acc[i][2] * scale, acc[i][3] * scale);
        float2 v2 = make_float2(acc[i][4] * scale, acc[i][5] * scale);
        *(float2*)(row + 0) = v0; *(float2*)(row + 2) = v1; *(float2*)(row + 4) = v2;
    }
}

// ---------------------------------------------------------------------------
// in-place softmax over last dim (96). one warp per row, 3 values per lane.
// ---------------------------------------------------------------------------
__global__ __launch_bounds__(256) void softmax_kernel(float* __restrict__ S)
{
    const int row = blockIdx.x * 8 + (threadIdx.x >> 5);
    const int lane = threadIdx.x & 31;
    float* p = S + (size_t)row * MM;
    float v0 = p[lane], v1 = p[lane + 32], v2 = p[lane + 64];
    float mx = fmaxf(v0, fmaxf(v1, v2));
#pragma unroll
    for (int o = 16; o > 0; o >>= 1)
        mx = fmaxf(mx, __shfl_xor_sync(0xffffffffu, mx, o));
    v0 = __expf(v0 - mx); v1 = __expf(v1 - mx); v2 = __expf(v2 - mx);
    float sm = v0 + v1 + v2;
#pragma unroll
    for (int o = 16; o > 0; o >>= 1)
        sm += __shfl_xor_sync(0xffffffffu, sm, o);
    float inv = 1.f / sm;
    p[lane] = v0 * inv; p[lane + 32] = v1 * inv; p[lane + 64] = v2 * inv;
}

// ---------------------------------------------------------------------------
// Sequential erase/add scan over W + fused LayerNorm.
// Block: (b, m-chunk of 48). 256 threads, each owns d = (2*tid, 2*tid+1)
// -> full D=512 per block, so LN reduces inside the block.
// ---------------------------------------------------------------------------
__global__ __launch_bounds__(256) void update_ln_kernel(
    const float* __restrict__ mem, const float* __restrict__ attn,
    const float* __restrict__ E, const float* __restrict__ Aadd,
    const float* __restrict__ gamma, const float* __restrict__ beta,
    float* __restrict__ out)
{
    const int b = blockIdx.y;
    const int m0 = blockIdx.x * 48;
    const int tid = threadIdx.x;

    __shared__ float a_s[WW * 48];   // attn[b, :, m0:m0+48]   24 KB
    __shared__ float redS[8], redQ[8];

    float s0[48], s1[48];
    const float2* memp = (const float2*)mem + (size_t)(b * MM + m0) * 256;
#pragma unroll
    for (int m = 0; m < 48; m++) {
        float2 v = memp[m * 256 + tid];
        s0[m] = v.x; s1[m] = v.y;
    }
    for (int idx = tid; idx < WW * 48; idx += 256) {
        int w = idx / 48, mm = idx % 48;
        a_s[idx] = attn[((size_t)(b * WW + w)) * MM + m0 + mm];
    }
    __syncthreads();

    const float2* Ep = (const float2*)E    + (size_t)b * WW * 256 + tid;
    const float2* Ap = (const float2*)Aadd + (size_t)b * WW * 256 + tid;

    for (int w = 0; w < WW; w++) {
        float2 e2 = Ep[w * 256];
        float2 d2 = Ap[w * 256];
        float nex = -e2.x, ney = -e2.y;
        const float* arow = &a_s[w * 48];
#pragma unroll
        for (int m = 0; m < 48; m++) {
            float c = arow[m];
            float t0 = fmaf(nex, s0[m], d2.x);
            s0[m] = fmaf(c, t0, s0[m]);
            float t1 = fmaf(ney, s1[m], d2.y);
            s1[m] = fmaf(c, t1, s1[m]);
        }
    }

    // fused LayerNorm over D for each of the 48 rows
    const float2 g2 = ((const float2*)gamma)[tid];
    const float2 bt2 = ((const float2*)beta)[tid];
    const int wid = tid >> 5, lane = tid & 31;
    float2* outp = (float2*)out + (size_t)(b * MM + m0) * 256 + tid;

    for (int m = 0; m < 48; m++) {
        float sm = s0[m] + s1[m];
        float sq = fmaf(s0[m], s0[m], s1[m] * s1[m]);
#pragma unroll
        for (int o = 16; o > 0; o >>= 1) {
            sm += __shfl_xor_sync(0xffffffffu, sm, o);
            sq += __shfl_xor_sync(0xffffffffu, sq, o);
        }
        if (lane == 0) { redS[wid] = sm; redQ[wid] = sq; }
        __syncthreads();
        float S = 0.f, Q = 0.f;
#pragma unroll
        for (int i = 0; i < 8; i++) { S += redS[i]; Q += redQ[i]; }
        __syncthreads();   // protect red arrays before next m
        float mu = S * (1.f / 512.f);
        float var = Q * (1.f / 512.f) - mu * mu;
        float rs = rsqrtf(var + 1e-5f);
        float o0 = fmaf((s0[m] - mu) * rs, g2.x, bt2.x);
        float o1 = fmaf((s1[m] - mu) * rs, g2.y, bt2.y);
        outp[m * 256] = make_float2(o0, o1);
    }
}

// ---------------------------------------------------------------------------
extern "C" void kernel_launch(void* const* d_in, const int* in_sizes, int n_in,
                              void* d_out, int out_size)
{
    const float* memory = (const float*)d_in[0];
    const float* wtok   = (const float*)d_in[1];
    const float* Wq = (const float*)d_in[2];  const float* bq = (const float*)d_in[3];
    const float* Wk = (const float*)d_in[4];  const float* bk = (const float*)d_in[5];
    const float* We = (const float*)d_in[6];  const float* be = (const float*)d_in[7];
    const float* Wa = (const float*)d_in[8];  const float* ba = (const float*)d_in[9];
    const float* gamma = (const float*)d_in[10];
    const float* beta  = (const float*)d_in[11];
    float* out = (float*)d_out;

    float *q, *e, *a, *k, *s;
    cudaGetSymbolAddress((void**)&q, g_q);
    cudaGetSymbolAddress((void**)&e, g_e);
    cudaGetSymbolAddress((void**)&a, g_a);
    cudaGetSymbolAddress((void**)&k, g_k);
    cudaGetSymbolAddress((void**)&s, g_s);

    // q / erase / add from write_tokens [32768 x 512]
    gemm_xwT_kernel<<<dim3(512, 8), 256>>>(wtok, Wq, bq, q, 0);
    gemm_xwT_kernel<<<dim3(512, 8), 256>>>(wtok, We, be, e, 1);
    gemm_xwT_kernel<<<dim3(512, 8), 256>>>(wtok, Wa, ba, a, 2);
    // k from memory [24576 x 512]
    gemm_xwT_kernel<<<dim3(384, 8), 256>>>(memory, Wk, bk, k, 0);
    // attention scores + softmax
    scores_kernel<<<dim3(2, BB), 256>>>(q, k, s);
    softmax_kernel<<<BB * WW / 8, 256>>>(s);
    // sequential write scan + layernorm
    update_ln_kernel<<<dim3(2, BB), 256>>>(memory, s, e, a, gamma, beta, out);
}

// round 2
// speedup vs baseline: 3.2634x; 3.2634x over previous
#include <cuda_runtime.h>
#include <cuda_bf16.h>
#include <cstdint>

// Problem constants
#define BB 256   // batch
#define MM 96    // memory slots
#define WW 128   // write tokens
#define DD 512   // embed dim

// ---------------- scratch (static device globals: allocation-free) ----------
__device__ __nv_bfloat16 g_wtok_bf[BB * WW * DD];
__device__ __nv_bfloat16 g_mem_bf[BB * MM * DD];
__device__ __nv_bfloat16 g_Wq_bf[DD * DD];
__device__ __nv_bfloat16 g_Wk_bf[DD * DD];
__device__ __nv_bfloat16 g_We_bf[DD * DD];
__device__ __nv_bfloat16 g_Wa_bf[DD * DD];

__device__ float g_q[BB * WW * DD];
__device__ float g_k[BB * MM * DD];
__device__ float g_e[BB * WW * DD];
__device__ float g_a[BB * WW * DD];
__device__ float g_s[BB * WW * MM];

static __device__ __forceinline__ uint32_t smem_u32(const void* p) {
    uint32_t a;
    asm("{ .reg .u64 t; cvta.to.shared.u64 t, %1; cvt.u32.u64 %0, t; }" : "=r"(a) : "l"(p));
    return a;
}

// ---------------------------------------------------------------------------
// fp32 -> bf16 conversion (vectorized, grid-stride)
// ---------------------------------------------------------------------------
__global__ __launch_bounds__(256) void f2bf_kernel(
    const float4* __restrict__ src, uint2* __restrict__ dst, int n4)
{
    int i = blockIdx.x * 256 + threadIdx.x;
    int stride = gridDim.x * 256;
    for (; i < n4; i += stride) {
        float4 v = src[i];
        __nv_bfloat162 lo = __floats2bfloat162_rn(v.x, v.y);
        __nv_bfloat162 hi = __floats2bfloat162_rn(v.z, v.w);
        uint2 o;
        o.x = *(uint32_t*)&lo;
        o.y = *(uint32_t*)&hi;
        dst[i] = o;
    }
}

// ---------------------------------------------------------------------------
// Tensor-core GEMM: C[r, n] = act( sum_k A[r,k] * Bw[n,k] + bias[n] )
// A: [R, 512] bf16 row-major; Bw: [512, 512] bf16 row-major (n rows, k contig)
// Tile 128x128x32, 256 threads (8 warps, 2x4), warp tile 64x32, mma m16n8k16.
// cp.async double buffer; smem rows padded to 40 bf16 (80B) -> conflict-free
// ldmatrix (5r mod 8 distinct 16B phases).
// act: 0=none, 1=sigmoid, 2=tanh
// ---------------------------------------------------------------------------
#define GBM 128
#define GBN 128
#define GBK 32
#define LDSK 40
#define NKT (DD / GBK)   // 16

__global__ __launch_bounds__(256) void mma_gemm_kernel(
    const __nv_bfloat16* __restrict__ A,
    const __nv_bfloat16* __restrict__ Bw,
    const float* __restrict__ bias,
    float* __restrict__ C, int act)
{
    __shared__ __nv_bfloat16 sA[2][GBM * LDSK];
    __shared__ __nv_bfloat16 sB[2][GBN * LDSK];

    const int tid = threadIdx.x;
    const int wid = tid >> 5;
    const int lane = tid & 31;
    const int wm = wid & 1;       // 2 warps along m
    const int wn = wid >> 1;      // 4 warps along n
    const long rowbase = (long)blockIdx.x * GBM;
    const int colbase = blockIdx.y * GBN;

    float acc[4][4][4];
#pragma unroll
    for (int mi = 0; mi < 4; mi++)
#pragma unroll
        for (int ni = 0; ni < 4; ni++)
#pragma unroll
            for (int v = 0; v < 4; v++) acc[mi][ni][v] = 0.f;

    const uint32_t sA_base = smem_u32(&sA[0][0]);
    const uint32_t sB_base = smem_u32(&sB[0][0]);

    // staging: 512 16B chunks per tile; thread handles chunks tid and tid+256
    const int ar0 = tid >> 2, ac0 = (tid & 3) * 8;
    const int c1 = tid + 256;
    const int ar1 = c1 >> 2, ac1 = (c1 & 3) * 8;

#define STAGE(buf, kt) do {                                                        \
    const int kk_ = (kt) * GBK;                                                    \
    const __nv_bfloat16* ga0 = A  + (rowbase + ar0) * DD + kk_ + ac0;              \
    const __nv_bfloat16* ga1 = A  + (rowbase + ar1) * DD + kk_ + ac1;              \
    const __nv_bfloat16* gb0 = Bw + (long)(colbase + ar0) * DD + kk_ + ac0;        \
    const __nv_bfloat16* gb1 = Bw + (long)(colbase + ar1) * DD + kk_ + ac1;        \
    uint32_t s_;                                                                   \
    s_ = sA_base + (uint32_t)(((buf) * GBM * LDSK + ar0 * LDSK + ac0) * 2);        \
    asm volatile("cp.async.cg.shared.global [%0], [%1], 16;\n" :: "r"(s_), "l"(ga0)); \
    s_ = sA_base + (uint32_t)(((buf) * GBM * LDSK + ar1 * LDSK + ac1) * 2);        \
    asm volatile("cp.async.cg.shared.global [%0], [%1], 16;\n" :: "r"(s_), "l"(ga1)); \
    s_ = sB_base + (uint32_t)(((buf) * GBN * LDSK + ar0 * LDSK + ac0) * 2);        \
    asm volatile("cp.async.cg.shared.global [%0], [%1], 16;\n" :: "r"(s_), "l"(gb0)); \
    s_ = sB_base + (uint32_t)(((buf) * GBN * LDSK + ar1 * LDSK + ac1) * 2);        \
    asm volatile("cp.async.cg.shared.global [%0], [%1], 16;\n" :: "r"(s_), "l"(gb1)); \
    asm volatile("cp.async.commit_group;\n");                                      \
} while (0)

    STAGE(0, 0);

    for (int kt = 0; kt < NKT; kt++) {
        if (kt + 1 < NKT) {
            STAGE((kt + 1) & 1, kt + 1);
            asm volatile("cp.async.wait_group 1;\n");
        } else {
            asm volatile("cp.async.wait_group 0;\n");
        }
        __syncthreads();

        const int buf = kt & 1;
#pragma unroll
        for (int ks = 0; ks < 2; ks++) {
            const int k0 = ks * 16;

            uint32_t af[4][4];
#pragma unroll
            for (int mi = 0; mi < 4; mi++) {
                const int m0 = wm * 64 + mi * 16;
                uint32_t addr = sA_base + (uint32_t)((buf * GBM * LDSK +
                    (m0 + (lane & 15)) * LDSK + k0 + ((lane >> 4) * 8)) * 2);
                asm volatile(
                    "ldmatrix.sync.aligned.m8n8.x4.shared.b16 {%0,%1,%2,%3}, [%4];\n"
                    : "=r"(af[mi][0]), "=r"(af[mi][1]), "=r"(af[mi][2]), "=r"(af[mi][3])
                    : "r"(addr));
            }

            uint32_t bf[4][2];
#pragma unroll
            for (int nj = 0; nj < 2; nj++) {
                const int n0 = wn * 32 + nj * 16;
                uint32_t addr = sB_base + (uint32_t)((buf * GBN * LDSK +
                    (n0 + (lane & 7) + ((lane >> 4) << 3)) * LDSK +
                    k0 + (((lane >> 3) & 1) * 8)) * 2);
                uint32_t r0, r1, r2, r3;
                asm volatile(
                    "ldmatrix.sync.aligned.m8n8.x4.shared.b16 {%0,%1,%2,%3}, [%4];\n"
                    : "=r"(r0), "=r"(r1), "=r"(r2), "=r"(r3) : "r"(addr));
                bf[nj * 2][0] = r0;     bf[nj * 2][1] = r1;
                bf[nj * 2 + 1][0] = r2; bf[nj * 2 + 1][1] = r3;
            }

#pragma unroll
            for (int mi = 0; mi < 4; mi++)
#pragma unroll
                for (int ni = 0; ni < 4; ni++)
                    asm volatile(
                        "mma.sync.aligned.m16n8k16.row.col.f32.bf16.bf16.f32 "
                        "{%0,%1,%2,%3}, {%4,%5,%6,%7}, {%8,%9}, {%0,%1,%2,%3};\n"
                        : "+f"(acc[mi][ni][0]), "+f"(acc[mi][ni][1]),
                          "+f"(acc[mi][ni][2]), "+f"(acc[mi][ni][3])
                        : "r"(af[mi][0]), "r"(af[mi][1]), "r"(af[mi][2]), "r"(af[mi][3]),
                          "r"(bf[ni][0]), "r"(bf[ni][1]));
        }
        __syncthreads();
    }

    // epilogue: bias + activation, fp32 out
#pragma unroll
    for (int mi = 0; mi < 4; mi++) {
        const long r0 = rowbase + wm * 64 + mi * 16 + (lane >> 2);
#pragma unroll
        for (int ni = 0; ni < 4; ni++) {
            const int col = colbase + wn * 32 + ni * 8 + (lane & 3) * 2;
            const float b0 = bias[col], b1 = bias[col + 1];
            float v0 = acc[mi][ni][0] + b0;
            float v1 = acc[mi][ni][1] + b1;
            float v2 = acc[mi][ni][2] + b0;
            float v3 = acc[mi][ni][3] + b1;
            if (act == 1) {
                v0 = 1.f / (1.f + __expf(-v0)); v1 = 1.f / (1.f + __expf(-v1));
                v2 = 1.f / (1.f + __expf(-v2)); v3 = 1.f / (1.f + __expf(-v3));
            } else if (act == 2) {
                v0 = tanhf(v0); v1 = tanhf(v1);
                v2 = tanhf(v2); v3 = tanhf(v3);
            }
            *(float2*)&C[r0 * DD + col] = make_float2(v0, v1);
            *(float2*)&C[(r0 + 8) * DD + col] = make_float2(v2, v3);
        }
    }
#undef STAGE
}

// ---------------------------------------------------------------------------
// scores[b, w, m] = scale * sum_d q[b,w,d] * k[b,m,d]   (fp32 SIMT)
// ---------------------------------------------------------------------------
__global__ __launch_bounds__(256) void scores_kernel(
    const float* __restrict__ Q, const float* __restrict__ K, float* __restrict__ S)
{
    __shared__ float qs[16][64];
    __shared__ float ks[16][96];

    const int b = blockIdx.y;
    const int w0 = blockIdx.x * 64;
    const int tid = threadIdx.x;
    const int tx = tid & 15;
    const int ty = tid >> 4;

    float acc[4][6];
#pragma unroll
    for (int i = 0; i < 4; i++)
#pragma unroll
        for (int j = 0; j < 6; j++) acc[i][j] = 0.f;

    const int qrow = tid >> 2;
    const int qcol = (tid & 3) * 4;
    const float* Qp = Q + ((size_t)(b * WW + w0 + qrow)) * DD + qcol;
    const float* Kb = K + (size_t)b * MM * DD;

    for (int k0 = 0; k0 < DD; k0 += 16) {
        float4 qa = *(const float4*)(Qp + k0);
        qs[qcol + 0][qrow] = qa.x; qs[qcol + 1][qrow] = qa.y;
        qs[qcol + 2][qrow] = qa.z; qs[qcol + 3][qrow] = qa.w;
        {
            int s = tid;
            int kr = s >> 2, kc = (s & 3) * 4;
            float4 kv = *(const float4*)(Kb + (size_t)kr * DD + k0 + kc);
            ks[kc + 0][kr] = kv.x; ks[kc + 1][kr] = kv.y;
            ks[kc + 2][kr] = kv.z; ks[kc + 3][kr] = kv.w;
            if (tid < 128) {
                s = tid + 256; kr = s >> 2; kc = (s & 3) * 4;
                kv = *(const float4*)(Kb + (size_t)kr * DD + k0 + kc);
                ks[kc + 0][kr] = kv.x; ks[kc + 1][kr] = kv.y;
                ks[kc + 2][kr] = kv.z; ks[kc + 3][kr] = kv.w;
            }
        }
        __syncthreads();
#pragma unroll
        for (int kk = 0; kk < 16; kk++) {
            float4 a = *(const float4*)&qs[kk][ty * 4];
            float2 p0 = *(const float2*)&ks[kk][tx * 6 + 0];
            float2 p1 = *(const float2*)&ks[kk][tx * 6 + 2];
            float2 p2 = *(const float2*)&ks[kk][tx * 6 + 4];
            float bj[6] = {p0.x, p0.y, p1.x, p1.y, p2.x, p2.y};
            float ai[4] = {a.x, a.y, a.z, a.w};
#pragma unroll
            for (int i = 0; i < 4; i++)
#pragma unroll
                for (int j = 0; j < 6; j++)
                    acc[i][j] = fmaf(ai[i], bj[j], acc[i][j]);
        }
        __syncthreads();
    }

    const float scale = 0.04419417382415922f;  // 1/sqrt(512)
#pragma unroll
    for (int i = 0; i < 4; i++) {
        float* row = S + ((size_t)(b * WW + w0 + ty * 4 + i)) * MM + tx * 6;
        float2 v0 = make_float2(acc[i][0] * scale, acc[i][1] * scale);
        float2 v1 = make_float2(acc[i][2] * scale, acc[i][3] * scale);
        float2 v2 = make_float2(acc[i][4] * scale, acc[i][5] * scale);
        *(float2*)(row + 0) = v0; *(float2*)(row + 2) = v1; *(float2*)(row + 4) = v2;
    }
}

// ---------------------------------------------------------------------------
// in-place softmax over last dim (96). one warp per row, 3 values per lane.
// ---------------------------------------------------------------------------
__global__ __launch_bounds__(256) void softmax_kernel(float* __restrict__ S)
{
    const int row = blockIdx.x * 8 + (threadIdx.x >> 5);
    const int lane = threadIdx.x & 31;
    float* p = S + (size_t)row * MM;
    float v0 = p[lane], v1 = p[lane + 32], v2 = p[lane + 64];
    float mx = fmaxf(v0, fmaxf(v1, v2));
#pragma unroll
    for (int o = 16; o > 0; o >>= 1)
        mx = fmaxf(mx, __shfl_xor_sync(0xffffffffu, mx, o));
    v0 = __expf(v0 - mx); v1 = __expf(v1 - mx); v2 = __expf(v2 - mx);
    float sm = v0 + v1 + v2;
#pragma unroll
    for (int o = 16; o > 0; o >>= 1)
        sm += __shfl_xor_sync(0xffffffffu, sm, o);
    float inv = 1.f / sm;
    p[lane] = v0 * inv; p[lane + 32] = v1 * inv; p[lane + 64] = v2 * inv;
}

// ---------------------------------------------------------------------------
// Sequential erase/add scan over W + fused LayerNorm.  (fp32 state)
// ---------------------------------------------------------------------------
__global__ __launch_bounds__(256) void update_ln_kernel(
    const float* __restrict__ mem, const float* __restrict__ attn,
    const float* __restrict__ E, const float* __restrict__ Aadd,
    const float* __restrict__ gamma, const float* __restrict__ beta,
    float* __restrict__ out)
{
    const int b = blockIdx.y;
    const int m0 = blockIdx.x * 48;
    const int tid = threadIdx.x;

    __shared__ float a_s[WW * 48];
    __shared__ float redS[8], redQ[8];

    float s0[48], s1[48];
    const float2* memp = (const float2*)mem + (size_t)(b * MM + m0) * 256;
#pragma unroll
    for (int m = 0; m < 48; m++) {
        float2 v = memp[m * 256 + tid];
        s0[m] = v.x; s1[m] = v.y;
    }
    for (int idx = tid; idx < WW * 48; idx += 256) {
        int w = idx / 48, mm = idx % 48;
        a_s[idx] = attn[((size_t)(b * WW + w)) * MM + m0 + mm];
    }
    __syncthreads();

    const float2* Ep = (const float2*)E    + (size_t)b * WW * 256 + tid;
    const float2* Ap = (const float2*)Aadd + (size_t)b * WW * 256 + tid;

    for (int w = 0; w < WW; w++) {
        float2 e2 = Ep[w * 256];
        float2 d2 = Ap[w * 256];
        float nex = -e2.x, ney = -e2.y;
        const float* arow = &a_s[w * 48];
#pragma unroll
        for (int m = 0; m < 48; m++) {
            float c = arow[m];
            float t0 = fmaf(nex, s0[m], d2.x);
            s0[m] = fmaf(c, t0, s0[m]);
            float t1 = fmaf(ney, s1[m], d2.y);
            s1[m] = fmaf(c, t1, s1[m]);
        }
    }

    const float2 g2 = ((const float2*)gamma)[tid];
    const float2 bt2 = ((const float2*)beta)[tid];
    const int wid = tid >> 5, lane = tid & 31;
    float2* outp = (float2*)out + (size_t)(b * MM + m0) * 256 + tid;

    for (int m = 0; m < 48; m++) {
        float sm = s0[m] + s1[m];
        float sq = fmaf(s0[m], s0[m], s1[m] * s1[m]);
#pragma unroll
        for (int o = 16; o > 0; o >>= 1) {
            sm += __shfl_xor_sync(0xffffffffu, sm, o);
            sq += __shfl_xor_sync(0xffffffffu, sq, o);
        }
        if (lane == 0) { redS[wid] = sm; redQ[wid] = sq; }
        __syncthreads();
        float S = 0.f, Q = 0.f;
#pragma unroll
        for (int i = 0; i < 8; i++) { S += redS[i]; Q += redQ[i]; }
        __syncthreads();
        float mu = S * (1.f / 512.f);
        float var = Q * (1.f / 512.f) - mu * mu;
        float rs = rsqrtf(var + 1e-5f);
        float o0 = fmaf((s0[m] - mu) * rs, g2.x, bt2.x);
        float o1 = fmaf((s1[m] - mu) * rs, g2.y, bt2.y);
        outp[m * 256] = make_float2(o0, o1);
    }
}

// ---------------------------------------------------------------------------
extern "C" void kernel_launch(void* const* d_in, const int* in_sizes, int n_in,
                              void* d_out, int out_size)
{
    const float* memory = (const float*)d_in[0];
    const float* wtok   = (const float*)d_in[1];
    const float* Wq = (const float*)d_in[2];  const float* bq = (const float*)d_in[3];
    const float* Wk = (const float*)d_in[4];  const float* bk = (const float*)d_in[5];
    const float* We = (const float*)d_in[6];  const float* be = (const float*)d_in[7];
    const float* Wa = (const float*)d_in[8];  const float* ba = (const float*)d_in[9];
    const float* gamma = (const float*)d_in[10];
    const float* beta  = (const float*)d_in[11];
    float* out = (float*)d_out;

    float *q, *k, *e, *a, *s;
    __nv_bfloat16 *wt_bf, *m_bf, *wq_bf, *wk_bf, *we_bf, *wa_bf;
    cudaGetSymbolAddress((void**)&q, g_q);
    cudaGetSymbolAddress((void**)&k, g_k);
    cudaGetSymbolAddress((void**)&e, g_e);
    cudaGetSymbolAddress((void**)&a, g_a);
    cudaGetSymbolAddress((void**)&s, g_s);
    cudaGetSymbolAddress((void**)&wt_bf, g_wtok_bf);
    cudaGetSymbolAddress((void**)&m_bf, g_mem_bf);
    cudaGetSymbolAddress((void**)&wq_bf, g_Wq_bf);
    cudaGetSymbolAddress((void**)&wk_bf, g_Wk_bf);
    cudaGetSymbolAddress((void**)&we_bf, g_We_bf);
    cudaGetSymbolAddress((void**)&wa_bf, g_Wa_bf);

    // fp32 -> bf16 conversions
    {
        int n4 = BB * WW * DD / 4;
        f2bf_kernel<<<(n4 + 255) / 256, 256>>>((const float4*)wtok, (uint2*)wt_bf, n4);
        n4 = BB * MM * DD / 4;
        f2bf_kernel<<<(n4 + 255) / 256, 256>>>((const float4*)memory, (uint2*)m_bf, n4);
        n4 = DD * DD / 4;
        f2bf_kernel<<<(n4 + 255) / 256, 256>>>((const float4*)Wq, (uint2*)wq_bf, n4);
        f2bf_kernel<<<(n4 + 255) / 256, 256>>>((const float4*)Wk, (uint2*)wk_bf, n4);
        f2bf_kernel<<<(n4 + 255) / 256, 256>>>((const float4*)We, (uint2*)we_bf, n4);
        f2bf_kernel<<<(n4 + 255) / 256, 256>>>((const float4*)Wa, (uint2*)wa_bf, n4);
    }

    // tensor-core GEMMs (fp32 accumulate, fp32 out, fused bias+activation)
    mma_gemm_kernel<<<dim3(BB * WW / GBM, DD / GBN), 256>>>(wt_bf, wq_bf, bq, q, 0);
    mma_gemm_kernel<<<dim3(BB * WW / GBM, DD / GBN), 256>>>(wt_bf, we_bf, be, e, 1);
    mma_gemm_kernel<<<dim3(BB * WW / GBM, DD / GBN), 256>>>(wt_bf, wa_bf, ba, a, 2);
    mma_gemm_kernel<<<dim3(BB * MM / GBM, DD / GBN), 256>>>(m_bf, wk_bf, bk, k, 0);

    // attention scores + softmax
    scores_kernel<<<dim3(2, BB), 256>>>(q, k, s);
    softmax_kernel<<<BB * WW / 8, 256>>>(s);

    // sequential write scan + fused layernorm
    update_ln_kernel<<<dim3(2, BB), 256>>>(memory, s, e, a, gamma, beta, out);
}